// round 3
// baseline (speedup 1.0000x reference)
#include <cuda_runtime.h>
#include <cuda_bf16.h>

#define BATCH 8
#define CH    3
#define TT    16
#define H     512
#define WID   512
#define S     224
#define RMAXF 1024.0f

// Block = (32, 8) = 256 threads, handles one plane's rows {y, y+112} for
// y = blockIdx.y*8 + ty  (blockIdx.y in [0,14)).  grid = (1, 14, 384).
// x-sampling LUT (shared by all 224 rows of the plane) built once in smem.
__global__ __launch_bounds__(256) void crop_prompter_kernel(
    const float* __restrict__ x,
    const int*   __restrict__ cam_views,
    const float* __restrict__ resize,
    const float* __restrict__ yoffs,
    const float* __restrict__ xoffs,
    float*       __restrict__ out)
{
    __shared__ float4 lut[S];   // {x0 bits, x1 bits, wx, 1-wx}

    const int plane = blockIdx.z;                 // b*C*T + c*T + t
    const int b     = plane / (CH * TT);
    const int tx    = threadIdx.x;
    const int ty    = threadIdx.y;

    // Per-camera params
    const int   cam   = __ldg(&cam_views[b]);
    const float r     = floorf(fminf(fmaxf(__ldg(&resize[cam]), (float)H), RMAXF));
    const float scale = (float)H / r;             // in [0.5, 1.0]
    const float yo    = floorf(fminf(fmaxf(__ldg(&yoffs[cam]), 0.0f), r - (float)S));
    const float xo    = floorf(fminf(fmaxf(__ldg(&xoffs[cam]), 0.0f), r - (float)S));

    // Build x LUT cooperatively (224 of 256 threads active)
    {
        const int idx = ty * 32 + tx;
        if (idx < S) {
            const float sx = fmaxf((xo + (float)idx + 0.5f) * scale - 0.5f, 0.0f);
            const int   x0 = (int)sx;             // sx in [0, 511.25] -> cast == floor
            const float wx = sx - (float)x0;
            const int   x1 = min(x0 + 1, WID - 1);
            lut[idx] = make_float4(__int_as_float(x0), __int_as_float(x1),
                                   wx, 1.0f - wx);
        }
    }
    __syncthreads();

    // Two output rows per warp: ysA in [0,112), ysB = ysA + 112
    const int ysA = blockIdx.y * 8 + ty;
    const int ysB = ysA + (S / 2);

    const float syA = fmaxf((yo + (float)ysA + 0.5f) * scale - 0.5f, 0.0f);
    const float syB = fmaxf((yo + (float)ysB + 0.5f) * scale - 0.5f, 0.0f);
    const int   yA0 = (int)syA;                   // <= 511, no clamp needed
    const int   yB0 = (int)syB;
    const int   yA1 = min(yA0 + 1, H - 1);
    const int   yB1 = min(yB0 + 1, H - 1);
    const float wyA = syA - (float)yA0, onewyA = 1.0f - wyA;
    const float wyB = syB - (float)yB0, onewyB = 1.0f - wyB;

    const float* __restrict__ p   = x + (size_t)plane * (H * WID);
    const float* __restrict__ rA0 = p + (size_t)yA0 * WID;
    const float* __restrict__ rA1 = p + (size_t)yA1 * WID;
    const float* __restrict__ rB0 = p + (size_t)yB0 * WID;
    const float* __restrict__ rB1 = p + (size_t)yB1 * WID;

    float* __restrict__ outA = out + (size_t)plane * (S * S) + (size_t)ysA * S + tx;
    float* __restrict__ outB = out + (size_t)plane * (S * S) + (size_t)ysB * S + tx;

    #pragma unroll
    for (int i = 0; i < 7; ++i) {
        const float4 L  = lut[tx + 32 * i];
        const int    x0 = __float_as_int(L.x);
        const int    x1 = __float_as_int(L.y);
        const float  wx = L.z, onewx = L.w;

        const float aA00 = __ldg(rA0 + x0);
        const float aA01 = __ldg(rA0 + x1);
        const float aA10 = __ldg(rA1 + x0);
        const float aA11 = __ldg(rA1 + x1);
        const float aB00 = __ldg(rB0 + x0);
        const float aB01 = __ldg(rB0 + x1);
        const float aB10 = __ldg(rB1 + x0);
        const float aB11 = __ldg(rB1 + x1);

        // y-lerp first (reference order), then x
        const float vA0 = aA00 * onewyA + aA10 * wyA;
        const float vA1 = aA01 * onewyA + aA11 * wyA;
        const float vB0 = aB00 * onewyB + aB10 * wyB;
        const float vB1 = aB01 * onewyB + aB11 * wyB;

        outA[32 * i] = vA0 * onewx + vA1 * wx;
        outB[32 * i] = vB0 * onewx + vB1 * wx;
    }
}

extern "C" void kernel_launch(void* const* d_in, const int* in_sizes, int n_in,
                              void* d_out, int out_size)
{
    const float* x    = (const float*)d_in[0];
    const int*   cams = (const int*)  d_in[1];
    const float* rz   = (const float*)d_in[2];
    const float* yo   = (const float*)d_in[3];
    const float* xo   = (const float*)d_in[4];
    float* out = (float*)d_out;

    dim3 block(32, 8, 1);
    dim3 grid(1, (S / 2) / 8, BATCH * CH * TT);
    crop_prompter_kernel<<<grid, block>>>(x, cams, rz, yo, xo, out);
}